// round 2
// baseline (speedup 1.0000x reference)
#include <cuda_runtime.h>
#include <math.h>

#define BB 8
#define SS 2048
#define KIN 128
#define NIN 256
#define NPROC 1024
#define KPROC 256
#define DM 1024

// ---------------- scratch (device globals; no allocation allowed) ----------------
__device__ float g_PWT[NIN * NPROC];          // process_weights^T  [256][1024]
__device__ float g_Wg[BB * KIN * NPROC];      // gathered weights   [8][128][1024]
__device__ float g_part[BB * 16 * NPROC];     // partial col sums   [8][16 mtiles][1024]
__device__ int   g_pidx[BB * KPROC];          // selected neurons   [8][256]
__device__ float g_Wsel[BB * KIN * KPROC];    // selected weights   [8][128][256]
__device__ float g_asel[BB * SS * KPROC];     // selected acts      [8][2048][256]

__device__ __forceinline__ float gelu_exact(float x) {
    return 0.5f * x * (1.0f + erff(x * 0.70710678118654752f));
}

// ---------------- K0: transpose process_weights [1024][256] -> PWT [256][1024] ----
__global__ void k_transpose(const float* __restrict__ pw) {
    __shared__ float t[32][33];
    int x = blockIdx.x * 32 + threadIdx.x;   // col in PW (0..255)
    int y = blockIdx.y * 32 + threadIdx.y;   // row in PW (0..1023)
    #pragma unroll
    for (int i = 0; i < 32; i += 8)
        t[threadIdx.y + i][threadIdx.x] = pw[(y + i) * NIN + x];
    __syncthreads();
    int x2 = blockIdx.y * 32 + threadIdx.x;  // col in PWT (= PW row)
    int y2 = blockIdx.x * 32 + threadIdx.y;  // row in PWT (= PW col)
    #pragma unroll
    for (int i = 0; i < 32; i += 8)
        g_PWT[(y2 + i) * NPROC + x2] = t[threadIdx.x][threadIdx.y + i];
}

// ---------------- K1: gather Wg[b][k][:] = PWT[input_idx[b][k]][:] -----------------
__global__ void k_gather_wg(const int* __restrict__ iidx) {
    int b = blockIdx.x / KIN;
    int k = blockIdx.x % KIN;
    int c = iidx[b * KIN + k];
    const float4* src = (const float4*)&g_PWT[(size_t)c * NPROC];
    float4* dst = (float4*)&g_Wg[((size_t)b * KIN + k) * NPROC];
    dst[threadIdx.x] = src[threadIdx.x];     // 256 thr * float4 = 1024 floats
}

// ---------------- K2: GEMM1 + gelu + per-tile column sums (deterministic) ----------
// grid (16 mtiles, 8 ntiles, 8 batch), 256 threads, 128x128 tile, 8x8 microtile
__global__ __launch_bounds__(256) void k_scores(const float* __restrict__ X) {
    __shared__ float As[16][128];
    __shared__ float Bs[16][128];
    int b = blockIdx.z;
    int m0 = blockIdx.x * 128;
    int n0 = blockIdx.y * 128;
    int tid = threadIdx.x;
    int tx = tid & 15, ty = tid >> 4;
    const float* A = X + (size_t)b * SS * KIN;                  // [2048][128]
    const float* Bm = g_Wg + (size_t)b * KIN * NPROC;           // [128][1024]
    float acc[8][8];
    #pragma unroll
    for (int i = 0; i < 8; i++)
        #pragma unroll
        for (int j = 0; j < 8; j++) acc[i][j] = 0.f;

    for (int kc = 0; kc < KIN; kc += 16) {
        #pragma unroll
        for (int it = 0; it < 2; it++) {      // A tile [128m][16k] -> As[k][m]
            int idx = tid + it * 256;
            int row = idx >> 2, c4 = idx & 3;
            float4 v = *(const float4*)&A[(m0 + row) * KIN + kc + c4 * 4];
            As[c4 * 4 + 0][row] = v.x; As[c4 * 4 + 1][row] = v.y;
            As[c4 * 4 + 2][row] = v.z; As[c4 * 4 + 3][row] = v.w;
        }
        #pragma unroll
        for (int it = 0; it < 2; it++) {      // B tile [16k][128n]
            int idx = tid + it * 256;
            int row = idx >> 5, c4 = idx & 31;
            *(float4*)&Bs[row][c4 * 4] =
                *(const float4*)&Bm[(kc + row) * NPROC + n0 + c4 * 4];
        }
        __syncthreads();
        #pragma unroll
        for (int kk = 0; kk < 16; kk++) {
            float a[8], bv[8];
            #pragma unroll
            for (int i = 0; i < 8; i++) a[i] = As[kk][ty * 8 + i];
            #pragma unroll
            for (int j = 0; j < 8; j++) bv[j] = Bs[kk][tx * 8 + j];
            #pragma unroll
            for (int i = 0; i < 8; i++)
                #pragma unroll
                for (int j = 0; j < 8; j++) acc[i][j] += a[i] * bv[j];
        }
        __syncthreads();
    }
    // gelu + column sums within thread, then reduce across 16 thread-rows via smem
    float cs[8];
    #pragma unroll
    for (int j = 0; j < 8; j++) {
        cs[j] = 0.f;
        #pragma unroll
        for (int i = 0; i < 8; i++) cs[j] += gelu_exact(acc[i][j]);
    }
    #pragma unroll
    for (int j = 0; j < 8; j++) As[ty][tx * 8 + j] = cs[j];   // reuse As [16][128]
    __syncthreads();
    if (tid < 128) {
        float s = 0.f;
        #pragma unroll
        for (int r = 0; r < 16; r++) s += As[r][tid];
        g_part[((size_t)b * 16 + blockIdx.x) * NPROC + n0 + tid] = s;
    }
}

// ---------------- K4: per-batch reduce + bitonic top-256 of 1024 + Wsel gather -----
__global__ __launch_bounds__(256) void k_topk() {
    __shared__ float sv[NPROC];
    __shared__ int   si[NPROC];
    int b = blockIdx.x;
    int tid = threadIdx.x;
    // reduce the 16 per-mtile partials in fixed order (deterministic)
    for (int t = tid; t < NPROC; t += 256) {
        float s = 0.f;
        #pragma unroll
        for (int r = 0; r < 16; r++) s += g_part[((size_t)b * 16 + r) * NPROC + t];
        sv[t] = s; si[t] = t;
    }
    __syncthreads();
    for (int k = 2; k <= NPROC; k <<= 1) {
        for (int j = k >> 1; j > 0; j >>= 1) {
            for (int t = tid; t < NPROC; t += 256) {
                int ixj = t ^ j;
                if (ixj > t) {
                    bool desc = ((t & k) == 0);
                    float v1 = sv[t], v2 = sv[ixj];
                    if ((v1 < v2) == desc) {
                        sv[t] = v2; sv[ixj] = v1;
                        int tmp = si[t]; si[t] = si[ixj]; si[ixj] = tmp;
                    }
                }
            }
            __syncthreads();
        }
    }
    for (int t = tid; t < KPROC; t += 256) g_pidx[b * KPROC + t] = si[t];
    // gather Wsel[b][k][j] = Wg[b][k][si[j]]
    for (int idx = tid; idx < KIN * KPROC; idx += 256) {
        int k = idx / KPROC, j = idx % KPROC;
        g_Wsel[((size_t)b * KIN + k) * KPROC + j] =
            g_Wg[((size_t)b * KIN + k) * NPROC + si[j]];
    }
}

// ---------------- K5: acts_sel = gelu(X @ Wsel)  [2048,128]x[128,256] --------------
// grid (16, 2, 8), same scheme as K2
__global__ __launch_bounds__(256) void k_actsel(const float* __restrict__ X) {
    __shared__ float As[16][128];
    __shared__ float Bs[16][128];
    int b = blockIdx.z;
    int m0 = blockIdx.x * 128;
    int n0 = blockIdx.y * 128;
    int tid = threadIdx.x;
    int tx = tid & 15, ty = tid >> 4;
    const float* A = X + (size_t)b * SS * KIN;
    const float* Bm = g_Wsel + (size_t)b * KIN * KPROC;         // [128][256]
    float acc[8][8];
    #pragma unroll
    for (int i = 0; i < 8; i++)
        #pragma unroll
        for (int j = 0; j < 8; j++) acc[i][j] = 0.f;

    for (int kc = 0; kc < KIN; kc += 16) {
        #pragma unroll
        for (int it = 0; it < 2; it++) {
            int idx = tid + it * 256;
            int row = idx >> 2, c4 = idx & 3;
            float4 v = *(const float4*)&A[(m0 + row) * KIN + kc + c4 * 4];
            As[c4 * 4 + 0][row] = v.x; As[c4 * 4 + 1][row] = v.y;
            As[c4 * 4 + 2][row] = v.z; As[c4 * 4 + 3][row] = v.w;
        }
        #pragma unroll
        for (int it = 0; it < 2; it++) {
            int idx = tid + it * 256;
            int row = idx >> 5, c4 = idx & 31;
            *(float4*)&Bs[row][c4 * 4] =
                *(const float4*)&Bm[(kc + row) * KPROC + n0 + c4 * 4];
        }
        __syncthreads();
        #pragma unroll
        for (int kk = 0; kk < 16; kk++) {
            float a[8], bv[8];
            #pragma unroll
            for (int i = 0; i < 8; i++) a[i] = As[kk][ty * 8 + i];
            #pragma unroll
            for (int j = 0; j < 8; j++) bv[j] = Bs[kk][tx * 8 + j];
            #pragma unroll
            for (int i = 0; i < 8; i++)
                #pragma unroll
                for (int j = 0; j < 8; j++) acc[i][j] += a[i] * bv[j];
        }
        __syncthreads();
    }
    #pragma unroll
    for (int i = 0; i < 8; i++) {
        int m = m0 + ty * 8 + i;
        float4 v0 = make_float4(gelu_exact(acc[i][0]), gelu_exact(acc[i][1]),
                                gelu_exact(acc[i][2]), gelu_exact(acc[i][3]));
        float4 v1 = make_float4(gelu_exact(acc[i][4]), gelu_exact(acc[i][5]),
                                gelu_exact(acc[i][6]), gelu_exact(acc[i][7]));
        float* dst = &g_asel[((size_t)b * SS + m) * KPROC + n0 + tx * 8];
        *(float4*)dst = v0;
        *(float4*)(dst + 4) = v1;
    }
}

// ---------------- K6: out = acts_sel @ gather(P)  [2048,256]x[256,1024] ------------
// grid (16, 8, 8)
__global__ __launch_bounds__(256) void k_out(const float* __restrict__ P,
                                             float* __restrict__ out) {
    __shared__ float As[16][128];
    __shared__ float Bs[16][128];
    int b = blockIdx.z;
    int m0 = blockIdx.x * 128;
    int n0 = blockIdx.y * 128;
    int tid = threadIdx.x;
    int tx = tid & 15, ty = tid >> 4;
    const float* A = g_asel + (size_t)b * SS * KPROC;           // [2048][256]
    const int* pidx = g_pidx + b * KPROC;
    float acc[8][8];
    #pragma unroll
    for (int i = 0; i < 8; i++)
        #pragma unroll
        for (int j = 0; j < 8; j++) acc[i][j] = 0.f;

    for (int kc = 0; kc < KPROC; kc += 16) {
        #pragma unroll
        for (int it = 0; it < 2; it++) {      // A tile [128m][16k] -> As[k][m]
            int idx = tid + it * 256;
            int row = idx >> 2, c4 = idx & 3;
            float4 v = *(const float4*)&A[(m0 + row) * KPROC + kc + c4 * 4];
            As[c4 * 4 + 0][row] = v.x; As[c4 * 4 + 1][row] = v.y;
            As[c4 * 4 + 2][row] = v.z; As[c4 * 4 + 3][row] = v.w;
        }
        #pragma unroll
        for (int it = 0; it < 2; it++) {      // B tile: gathered rows of P
            int idx = tid + it * 256;
            int row = idx >> 5, c4 = idx & 31;
            int pr = pidx[kc + row];
            *(float4*)&Bs[row][c4 * 4] =
                *(const float4*)&P[(size_t)pr * DM + n0 + c4 * 4];
        }
        __syncthreads();
        #pragma unroll
        for (int kk = 0; kk < 16; kk++) {
            float a[8], bv[8];
            #pragma unroll
            for (int i = 0; i < 8; i++) a[i] = As[kk][ty * 8 + i];
            #pragma unroll
            for (int j = 0; j < 8; j++) bv[j] = Bs[kk][tx * 8 + j];
            #pragma unroll
            for (int i = 0; i < 8; i++)
                #pragma unroll
                for (int j = 0; j < 8; j++) acc[i][j] += a[i] * bv[j];
        }
        __syncthreads();
    }
    #pragma unroll
    for (int i = 0; i < 8; i++) {
        int m = m0 + ty * 8 + i;
        float* dst = &out[((size_t)b * SS + m) * DM + n0 + tx * 8];
        *(float4*)dst = make_float4(acc[i][0], acc[i][1], acc[i][2], acc[i][3]);
        *(float4*)(dst + 4) = make_float4(acc[i][4], acc[i][5], acc[i][6], acc[i][7]);
    }
}

// ---------------- launch -----------------------------------------------------------
extern "C" void kernel_launch(void* const* d_in, const int* in_sizes, int n_in,
                              void* d_out, int out_size) {
    const float* X    = (const float*)d_in[0];   // [8,2048,128]
    const float* PW   = (const float*)d_in[1];   // [1024,256]
    const float* PO   = (const float*)d_in[2];   // [1024,1024]
    const int*   IIDX = (const int*)d_in[3];     // [8,128]

    k_transpose<<<dim3(NIN / 32, NPROC / 32), dim3(32, 8)>>>(PW);
    k_gather_wg<<<BB * KIN, 256>>>(IIDX);
    k_scores<<<dim3(16, 8, BB), 256>>>(X);
    k_topk<<<BB, 256>>>();
    k_actsel<<<dim3(16, 2, BB), 256>>>(X);
    k_out<<<dim3(16, 8, BB), 256>>>(PO, (float*)d_out);
}